// round 1
// baseline (speedup 1.0000x reference)
#include <cuda_runtime.h>
#include <cuda_bf16.h>
#include <math.h>

#define BB   4
#define L1C  1024
#define L2C  512
#define LT   1536
#define DPG  2304
#define DEX  1024
#define NH   8
#define NKV  4
#define DHD  256
#define QK_SCALE 0.0625f

// ---------------- scratch (device globals; no allocation allowed) ----------
__device__ float g_Q[(size_t)BB * LT * NH * DHD];    // [b, l, h, d]
__device__ float g_K[(size_t)BB * LT * NKV * DHD];   // [b, l, hkv, d]
__device__ float g_V[(size_t)BB * LT * NKV * DHD];
__device__ float g_att[(size_t)BB * LT * NH * DHD];  // attention output

// ---------------- generic NT GEMM: C[m,n] = sum_k A[m,k] * W[n,k] ----------
// Logical row m maps to physical row: (m / rpb) * bstride + off + (m % rpb)
// (identity mapping: rpb = M, bstride = 0, off = 0)
#define BM 64
#define BN 64
#define BK 16

__global__ __launch_bounds__(256) void gemm_nt(
    const float* __restrict__ A, const float* __restrict__ W,
    float* __restrict__ C, int M, int N, int K,
    int a_rpb, int a_bstride, int a_off,
    int c_rpb, int c_bstride, int c_off, int ldc)
{
    __shared__ float As[BK][BM + 1];
    __shared__ float Ws[BK][BN + 1];

    const int tid = threadIdx.x;
    const int bm = blockIdx.y * BM;
    const int bn = blockIdx.x * BN;
    const int tx = tid & 15;
    const int ty = tid >> 4;

    // staging: each thread loads one float4 of A tile and one of W tile
    const int lrow = tid >> 2;        // 0..63
    const int lc4  = (tid & 3) << 2;  // 0,4,8,12
    const int am = bm + lrow;
    const int ar = (am / a_rpb) * a_bstride + a_off + (am % a_rpb);
    const float* Ap = A + (size_t)ar * K + lc4;
    const float* Wp = W + (size_t)(bn + lrow) * K + lc4;

    float acc[4][4] = {};

    for (int k0 = 0; k0 < K; k0 += BK) {
        const float4 av = *(const float4*)(Ap + k0);
        const float4 wv = *(const float4*)(Wp + k0);
        __syncthreads();
        As[lc4 + 0][lrow] = av.x; As[lc4 + 1][lrow] = av.y;
        As[lc4 + 2][lrow] = av.z; As[lc4 + 3][lrow] = av.w;
        Ws[lc4 + 0][lrow] = wv.x; Ws[lc4 + 1][lrow] = wv.y;
        Ws[lc4 + 2][lrow] = wv.z; Ws[lc4 + 3][lrow] = wv.w;
        __syncthreads();
#pragma unroll
        for (int kk = 0; kk < BK; kk++) {
            const float a0 = As[kk][ty],      a1 = As[kk][ty + 16];
            const float a2 = As[kk][ty + 32], a3 = As[kk][ty + 48];
            const float w0 = Ws[kk][tx],      w1 = Ws[kk][tx + 16];
            const float w2 = Ws[kk][tx + 32], w3 = Ws[kk][tx + 48];
            acc[0][0] += a0 * w0; acc[0][1] += a0 * w1; acc[0][2] += a0 * w2; acc[0][3] += a0 * w3;
            acc[1][0] += a1 * w0; acc[1][1] += a1 * w1; acc[1][2] += a1 * w2; acc[1][3] += a1 * w3;
            acc[2][0] += a2 * w0; acc[2][1] += a2 * w1; acc[2][2] += a2 * w2; acc[2][3] += a2 * w3;
            acc[3][0] += a3 * w0; acc[3][1] += a3 * w1; acc[3][2] += a3 * w2; acc[3][3] += a3 * w3;
        }
    }

#pragma unroll
    for (int i = 0; i < 4; i++) {
        const int m = bm + ty + 16 * i;
        const int cr = (m / c_rpb) * c_bstride + c_off + (m % c_rpb);
        float* Cp = C + (size_t)cr * ldc + bn + tx;
        Cp[0]  = acc[i][0];
        Cp[16] = acc[i][1];
        Cp[32] = acc[i][2];
        Cp[48] = acc[i][3];
    }
}

// ---------------- RoPE (half-split rotation), optional fold of QK scale ----
__global__ void rope_kernel(float* __restrict__ X, const float* __restrict__ cs,
                            const float* __restrict__ sn, int nheads, float scale)
{
    const int h = blockIdx.x;
    const int l = blockIdx.y;
    const int b = blockIdx.z;
    const int i = threadIdx.x;  // 0..127
    const size_t row = (size_t)b * LT + l;
    const float c = cs[row * (DHD / 2) + i];
    const float s = sn[row * (DHD / 2) + i];
    const size_t base = (row * nheads + h) * DHD;
    const float x1 = X[base + i];
    const float x2 = X[base + (DHD / 2) + i];
    X[base + i]             = (x1 * c - x2 * s) * scale;
    X[base + (DHD / 2) + i] = (x2 * c + x1 * s) * scale;
}

// ---------------- flash-style attention ------------------------------------
// Block: 256 threads, one (b, h, 32-query tile). Online softmax over 48 key
// tiles of 32. Thread t: query q = t/8, lane a = t%8 owns dims {a + 8*i}.
#define ATT_STRIDE 260  // 256 + 4 pad: conflict-free for both access patterns
#define SMEM_ATTN ((3 * 32 * ATT_STRIDE + 32 * 32) * 4)

__global__ __launch_bounds__(256, 2) void attn_kernel(const float* __restrict__ mask)
{
    extern __shared__ float sm[];
    float* Qs = sm;
    float* Ks = sm + 32 * ATT_STRIDE;
    float* Vs = sm + 2 * 32 * ATT_STRIDE;
    float* S  = sm + 3 * 32 * ATT_STRIDE;  // [32][32]

    const int tid = threadIdx.x;
    const int qt = blockIdx.x;   // 0..47
    const int h  = blockIdx.y;   // 0..7
    const int b  = blockIdx.z;   // 0..3
    const int hkv = h >> 1;      // GQA rep = 2
    const int q = tid >> 3;      // 0..31
    const int a = tid & 7;       // 0..7

    // stage Q tile (32 rows x 256)
    for (int idx = tid; idx < 32 * 64; idx += 256) {
        const int row = idx >> 6;
        const int c4  = idx & 63;
        const float4 v = *(const float4*)&g_Q[((((size_t)b * LT + qt * 32 + row) * NH + h) * DHD) + c4 * 4];
        *(float4*)&Qs[row * ATT_STRIDE + c4 * 4] = v;
    }

    float acc[32];
#pragma unroll
    for (int i = 0; i < 32; i++) acc[i] = 0.f;
    float mrun = -1e30f, lrun = 0.f;

    const size_t mrow = ((size_t)b * LT + (qt * 32 + q)) * LT;

    for (int kt = 0; kt < LT / 32; kt++) {
        __syncthreads();  // previous tile's S/Vs fully consumed
        for (int idx = tid; idx < 32 * 64; idx += 256) {
            const int row = idx >> 6;
            const int c4  = idx & 63;
            const size_t gbase = ((((size_t)b * LT + kt * 32 + row) * NKV + hkv) * DHD) + c4 * 4;
            *(float4*)&Ks[row * ATT_STRIDE + c4 * 4] = *(const float4*)&g_K[gbase];
            *(float4*)&Vs[row * ATT_STRIDE + c4 * 4] = *(const float4*)&g_V[gbase];
        }
        __syncthreads();

        // S: thread computes keys {a, a+8, a+16, a+24} for query q
        {
            const float4* qp = (const float4*)&Qs[q * ATT_STRIDE];
            const float4* k0 = (const float4*)&Ks[(a +  0) * ATT_STRIDE];
            const float4* k1 = (const float4*)&Ks[(a +  8) * ATT_STRIDE];
            const float4* k2 = (const float4*)&Ks[(a + 16) * ATT_STRIDE];
            const float4* k3 = (const float4*)&Ks[(a + 24) * ATT_STRIDE];
            float s0 = 0.f, s1 = 0.f, s2 = 0.f, s3 = 0.f;
#pragma unroll 8
            for (int i = 0; i < 64; i++) {
                const float4 qv = qp[i];
                float4 kv;
                kv = k0[i]; s0 += qv.x * kv.x + qv.y * kv.y + qv.z * kv.z + qv.w * kv.w;
                kv = k1[i]; s1 += qv.x * kv.x + qv.y * kv.y + qv.z * kv.z + qv.w * kv.w;
                kv = k2[i]; s2 += qv.x * kv.x + qv.y * kv.y + qv.z * kv.z + qv.w * kv.w;
                kv = k3[i]; s3 += qv.x * kv.x + qv.y * kv.y + qv.z * kv.z + qv.w * kv.w;
            }
            const size_t mbase = mrow + (size_t)kt * 32;
            S[q * 32 + a +  0] = s0 + mask[mbase + a +  0];
            S[q * 32 + a +  8] = s1 + mask[mbase + a +  8];
            S[q * 32 + a + 16] = s2 + mask[mbase + a + 16];
            S[q * 32 + a + 24] = s3 + mask[mbase + a + 24];
        }
        __syncthreads();

        // online softmax + PV for this tile
        float newm = mrun;
#pragma unroll
        for (int j = 0; j < 32; j++) newm = fmaxf(newm, S[q * 32 + j]);
        const float alpha = __expf(mrun - newm);
        lrun *= alpha;
#pragma unroll
        for (int i = 0; i < 32; i++) acc[i] *= alpha;
        float p[32];
#pragma unroll
        for (int j = 0; j < 32; j++) {
            p[j] = __expf(S[q * 32 + j] - newm);
            lrun += p[j];
        }
#pragma unroll 2
        for (int j = 0; j < 32; j++) {
            const float pj = p[j];
            const float* vrow = &Vs[j * ATT_STRIDE + a];
#pragma unroll
            for (int i = 0; i < 32; i++) acc[i] += pj * vrow[8 * i];
        }
        mrun = newm;
    }

    const float inv = 1.f / lrun;
    const size_t obase = (((size_t)b * LT + qt * 32 + q) * NH + h) * DHD;
#pragma unroll
    for (int i = 0; i < 32; i++) g_att[obase + a + 8 * i] = acc[i] * inv;
}

// ---------------- launch ----------------------------------------------------
extern "C" void kernel_launch(void* const* d_in, const int* in_sizes, int n_in,
                              void* d_out, int out_size)
{
    const float* pg   = (const float*)d_in[0];
    const float* ex   = (const float*)d_in[1];
    const float* cs   = (const float*)d_in[2];
    const float* sn   = (const float*)d_in[3];
    const float* mask = (const float*)d_in[4];
    const float* Wq0  = (const float*)d_in[5];
    const float* Wk0  = (const float*)d_in[6];
    const float* Wv0  = (const float*)d_in[7];
    const float* Wo0  = (const float*)d_in[8];
    const float* Wq1  = (const float*)d_in[9];
    const float* Wk1  = (const float*)d_in[10];
    const float* Wv1  = (const float*)d_in[11];
    const float* Wo1  = (const float*)d_in[12];
    float* out = (float*)d_out;

    float *Qd, *Kd, *Vd, *Ad;
    cudaGetSymbolAddress((void**)&Qd, g_Q);
    cudaGetSymbolAddress((void**)&Kd, g_K);
    cudaGetSymbolAddress((void**)&Vd, g_V);
    cudaGetSymbolAddress((void**)&Ad, g_att);

    const int MQ = NH * DHD;    // 2048
    const int MKV = NKV * DHD;  // 1024

    // --- QKV projections, pg stream (M = 4096, K = 2304) ---
    gemm_nt<<<dim3(MQ / BN, (BB * L1C) / BM), 256>>>(
        pg, Wq0, Qd, BB * L1C, MQ, DPG, BB * L1C, 0, 0, L1C, LT, 0, MQ);
    gemm_nt<<<dim3(MKV / BN, (BB * L1C) / BM), 256>>>(
        pg, Wk0, Kd, BB * L1C, MKV, DPG, BB * L1C, 0, 0, L1C, LT, 0, MKV);
    gemm_nt<<<dim3(MKV / BN, (BB * L1C) / BM), 256>>>(
        pg, Wv0, Vd, BB * L1C, MKV, DPG, BB * L1C, 0, 0, L1C, LT, 0, MKV);

    // --- QKV projections, ex stream (M = 2048, K = 1024) ---
    gemm_nt<<<dim3(MQ / BN, (BB * L2C) / BM), 256>>>(
        ex, Wq1, Qd, BB * L2C, MQ, DEX, BB * L2C, 0, 0, L2C, LT, L1C, MQ);
    gemm_nt<<<dim3(MKV / BN, (BB * L2C) / BM), 256>>>(
        ex, Wk1, Kd, BB * L2C, MKV, DEX, BB * L2C, 0, 0, L2C, LT, L1C, MKV);
    gemm_nt<<<dim3(MKV / BN, (BB * L2C) / BM), 256>>>(
        ex, Wv1, Vd, BB * L2C, MKV, DEX, BB * L2C, 0, 0, L2C, LT, L1C, MKV);

    // --- RoPE (fold softmax scale into Q) ---
    rope_kernel<<<dim3(NH, LT, BB), DHD / 2>>>(Qd, cs, sn, NH, QK_SCALE);
    rope_kernel<<<dim3(NKV, LT, BB), DHD / 2>>>(Kd, cs, sn, NKV, 1.0f);

    // --- attention ---
    cudaFuncSetAttribute(attn_kernel, cudaFuncAttributeMaxDynamicSharedMemorySize, SMEM_ATTN);
    attn_kernel<<<dim3(LT / 32, NH, BB), 256, SMEM_ATTN>>>(mask);

    // --- output projections ---
    gemm_nt<<<dim3(DPG / BN, (BB * L1C) / BM), 256>>>(
        Ad, Wo0, out, BB * L1C, DPG, MQ, L1C, LT, 0, BB * L1C, 0, 0, DPG);
    gemm_nt<<<dim3(DEX / BN, (BB * L2C) / BM), 256>>>(
        Ad, Wo1, out + (size_t)BB * L1C * DPG, BB * L2C, DEX, MQ,
        L2C, LT, L1C, BB * L2C, 0, 0, DEX);
}

// round 3
// speedup vs baseline: 1.5307x; 1.5307x over previous
#include <cuda_runtime.h>
#include <cuda_bf16.h>
#include <math.h>
#include <stdint.h>

#define BB   4
#define L1C  1024
#define L2C  512
#define LT   1536
#define DPG  2304
#define DEX  1024
#define NH   8
#define NKV  4
#define DHD  256
#define QK_SCALE 0.0625f

// ---------------- scratch (device globals; no allocation allowed) ----------
__device__ float g_Q[(size_t)BB * LT * NH * DHD];    // [b, l, h, d]
__device__ float g_K[(size_t)BB * LT * NKV * DHD];   // [b, l, hkv, d]
__device__ float g_V[(size_t)BB * LT * NKV * DHD];
__device__ float g_att[(size_t)BB * LT * NH * DHD];  // attention out (tf32-rounded bits)

// tf32-rounded copies of GEMM operands (fp32 bit layout, 10-bit mantissa)
#define OFF_PG   0u
#define OFF_EX   9437184u
#define OFF_WQ0  11534336u
#define OFF_WK0  16252928u
#define OFF_WV0  18612224u
#define OFF_WO0  20971520u
#define OFF_WQ1  25690112u
#define OFF_WK1  27787264u
#define OFF_WV1  28835840u
#define OFF_WO1  29884416u
#define CVT_TOTAL 31981568u
__device__ unsigned g_cvt[CVT_TOTAL];

// ---------------- tf32 conversion (round-to-nearest) ------------------------
__global__ void cvt_tf32(const float4* __restrict__ in, uint4* __restrict__ out, int n4)
{
    int i = blockIdx.x * blockDim.x + threadIdx.x;
    if (i < n4) {
        float4 v = in[i];
        uint4 o;
        asm("cvt.rna.tf32.f32 %0, %1;" : "=r"(o.x) : "f"(v.x));
        asm("cvt.rna.tf32.f32 %0, %1;" : "=r"(o.y) : "f"(v.y));
        asm("cvt.rna.tf32.f32 %0, %1;" : "=r"(o.z) : "f"(v.z));
        asm("cvt.rna.tf32.f32 %0, %1;" : "=r"(o.w) : "f"(v.w));
        out[i] = o;
    }
}

// ---------------- tf32 tensor-core NT GEMM ----------------------------------
// C[m,n] = sum_k A[m,k] * W[n,k].  A,W hold tf32-rounded fp32 bits.
// Block tile 128x128x32, 8 warps (warp tile 32x64), 2-stage cp.async pipeline.
// Logical row m -> physical row (m / rpb) * bstride + off + (m % rpb).
#define GLDA 36                    // smem row stride (floats): conflict-free frags
#define GBUF (128 * GLDA)          // u32 per tile buffer
#define GSMEM_BYTES (4 * GBUF * 4) // As[2] + Ws[2]

__device__ __forceinline__ void cpa16(uint32_t dst, const void* src)
{
    asm volatile("cp.async.cg.shared.global [%0], [%1], 16;" :: "r"(dst), "l"(src));
}

#define MMA_TF32(d, a, b)                                                     \
    asm volatile("mma.sync.aligned.m16n8k8.row.col.f32.tf32.tf32.f32 "        \
                 "{%0,%1,%2,%3}, {%4,%5,%6,%7}, {%8,%9}, {%0,%1,%2,%3};"      \
                 : "+f"(d[0]), "+f"(d[1]), "+f"(d[2]), "+f"(d[3])             \
                 : "r"(a[0]), "r"(a[1]), "r"(a[2]), "r"(a[3]),                \
                   "r"(b[0]), "r"(b[1]))

__global__ __launch_bounds__(256, 2) void gemm_tf32(
    const unsigned* __restrict__ A, const unsigned* __restrict__ W,
    float* __restrict__ C, int K,
    int a_rpb, int a_bstride, int a_off,
    int c_rpb, int c_bstride, int c_off, int ldc)
{
    extern __shared__ unsigned smem[];
    unsigned* As = smem;              // [2][128][GLDA]
    unsigned* Ws = smem + 2 * GBUF;   // [2][128][GLDA]

    const int tid    = threadIdx.x;
    const int wid    = tid >> 5;
    const int lane   = tid & 31;
    const int warp_m = wid >> 1;      // 0..3
    const int warp_n = wid & 1;       // 0..1
    const int bm = blockIdx.y * 128;
    const int bn = blockIdx.x * 128;

    // ---- global->smem staging: thread covers 16 floats of one row ----
    const int lrow = tid >> 1;            // 0..127
    const int lcol = (tid & 1) * 16;      // 0 or 16
    const int am = bm + lrow;
    const int ar = (am / a_rpb) * a_bstride + a_off + (am % a_rpb);
    const unsigned* Ag = A + (size_t)ar * K + lcol;
    const unsigned* Wg = W + (size_t)(bn + lrow) * K + lcol;

    const uint32_t sbase = (uint32_t)__cvta_generic_to_shared(smem);
    const uint32_t dA = sbase + (lrow * GLDA + lcol) * 4;
    const uint32_t dW = sbase + (2 * GBUF + lrow * GLDA + lcol) * 4;

    float acc[2][8][4];
#pragma unroll
    for (int i = 0; i < 2; i++)
#pragma unroll
        for (int j = 0; j < 8; j++)
#pragma unroll
            for (int r = 0; r < 4; r++) acc[i][j][r] = 0.f;

    const int nk = K >> 5;  // chunks of 32

    // prologue: chunk 0 -> buffer 0
    {
#pragma unroll
        for (int j = 0; j < 4; j++) cpa16(dA + j * 16, Ag + j * 4);
#pragma unroll
        for (int j = 0; j < 4; j++) cpa16(dW + j * 16, Wg + j * 4);
        asm volatile("cp.async.commit_group;");
    }

    const int lr = lane >> 2;   // 0..7
    const int lc = lane & 3;    // 0..3

    for (int kc = 0; kc < nk; kc++) {
        const int cur = kc & 1;
        if (kc + 1 < nk) {
            const int nxt = (kc + 1) & 1;
            const unsigned* ag = Ag + (kc + 1) * 32;
            const unsigned* wg = Wg + (kc + 1) * 32;
            const uint32_t oa = dA + nxt * (GBUF * 4);
            const uint32_t ow = dW + nxt * (GBUF * 4);
#pragma unroll
            for (int j = 0; j < 4; j++) cpa16(oa + j * 16, ag + j * 4);
#pragma unroll
            for (int j = 0; j < 4; j++) cpa16(ow + j * 16, wg + j * 4);
            asm volatile("cp.async.commit_group;");
            asm volatile("cp.async.wait_group 1;");
        } else {
            asm volatile("cp.async.wait_group 0;");
        }
        __syncthreads();

        const unsigned* as = As + cur * GBUF + (warp_m * 32 + lr) * GLDA + lc;
        const unsigned* ws = Ws + cur * GBUF + (warp_n * 64 + lr) * GLDA + lc;

#pragma unroll
        for (int ks = 0; ks < 4; ks++) {
            const int k0 = ks * 8;
            unsigned a[2][4], b[8][2];
#pragma unroll
            for (int mf = 0; mf < 2; mf++) {
                const unsigned* p = as + mf * 16 * GLDA + k0;
                a[mf][0] = p[0];
                a[mf][1] = p[8 * GLDA];
                a[mf][2] = p[4];
                a[mf][3] = p[8 * GLDA + 4];
            }
#pragma unroll
            for (int nf = 0; nf < 8; nf++) {
                const unsigned* p = ws + nf * 8 * GLDA + k0;
                b[nf][0] = p[0];
                b[nf][1] = p[4];
            }
#pragma unroll
            for (int mf = 0; mf < 2; mf++)
#pragma unroll
                for (int nf = 0; nf < 8; nf++)
                    MMA_TF32(acc[mf][nf], a[mf], b[nf]);
        }
        __syncthreads();
    }

    // ---- epilogue ----
#pragma unroll
    for (int mf = 0; mf < 2; mf++) {
        const int m0 = bm + warp_m * 32 + mf * 16 + lr;
        const int m1 = m0 + 8;
        const int r0 = (m0 / c_rpb) * c_bstride + c_off + (m0 % c_rpb);
        const int r1 = (m1 / c_rpb) * c_bstride + c_off + (m1 % c_rpb);
#pragma unroll
        for (int nf = 0; nf < 8; nf++) {
            const int col = bn + warp_n * 64 + nf * 8 + lc * 2;
            *(float2*)&C[(size_t)r0 * ldc + col] = make_float2(acc[mf][nf][0], acc[mf][nf][1]);
            *(float2*)&C[(size_t)r1 * ldc + col] = make_float2(acc[mf][nf][2], acc[mf][nf][3]);
        }
    }
}

// ---------------- RoPE (half-split rotation), optional fold of QK scale ----
__global__ void rope_kernel(float* __restrict__ X, const float* __restrict__ cs,
                            const float* __restrict__ sn, int nheads, float scale)
{
    const int h = blockIdx.x;
    const int l = blockIdx.y;
    const int b = blockIdx.z;
    const int i = threadIdx.x;  // 0..127
    const size_t row = (size_t)b * LT + l;
    const float c = cs[row * (DHD / 2) + i];
    const float s = sn[row * (DHD / 2) + i];
    const size_t base = (row * nheads + h) * DHD;
    const float x1 = X[base + i];
    const float x2 = X[base + (DHD / 2) + i];
    X[base + i]             = (x1 * c - x2 * s) * scale;
    X[base + (DHD / 2) + i] = (x2 * c + x1 * s) * scale;
}

// ---------------- flash-style attention (fp32) ------------------------------
#define ATT_STRIDE 260
#define SMEM_ATTN ((3 * 32 * ATT_STRIDE + 32 * 32) * 4)

__global__ __launch_bounds__(256, 2) void attn_kernel(const float* __restrict__ mask)
{
    extern __shared__ float sm[];
    float* Qs = sm;
    float* Ks = sm + 32 * ATT_STRIDE;
    float* Vs = sm + 2 * 32 * ATT_STRIDE;
    float* S  = sm + 3 * 32 * ATT_STRIDE;  // [32][32]

    const int tid = threadIdx.x;
    const int qt = blockIdx.x;
    const int h  = blockIdx.y;
    const int b  = blockIdx.z;
    const int hkv = h >> 1;
    const int q = tid >> 3;
    const int a = tid & 7;

    for (int idx = tid; idx < 32 * 64; idx += 256) {
        const int row = idx >> 6;
        const int c4  = idx & 63;
        const float4 v = *(const float4*)&g_Q[((((size_t)b * LT + qt * 32 + row) * NH + h) * DHD) + c4 * 4];
        *(float4*)&Qs[row * ATT_STRIDE + c4 * 4] = v;
    }

    float acc[32];
#pragma unroll
    for (int i = 0; i < 32; i++) acc[i] = 0.f;
    float mrun = -1e30f, lrun = 0.f;

    const size_t mrow = ((size_t)b * LT + (qt * 32 + q)) * LT;

    for (int kt = 0; kt < LT / 32; kt++) {
        __syncthreads();
        for (int idx = tid; idx < 32 * 64; idx += 256) {
            const int row = idx >> 6;
            const int c4  = idx & 63;
            const size_t gbase = ((((size_t)b * LT + kt * 32 + row) * NKV + hkv) * DHD) + c4 * 4;
            *(float4*)&Ks[row * ATT_STRIDE + c4 * 4] = *(const float4*)&g_K[gbase];
            *(float4*)&Vs[row * ATT_STRIDE + c4 * 4] = *(const float4*)&g_V[gbase];
        }
        __syncthreads();

        {
            const float4* qp = (const float4*)&Qs[q * ATT_STRIDE];
            const float4* k0 = (const float4*)&Ks[(a +  0) * ATT_STRIDE];
            const float4* k1 = (const float4*)&Ks[(a +  8) * ATT_STRIDE];
            const float4* k2 = (const float4*)&Ks[(a + 16) * ATT_STRIDE];
            const float4* k3 = (const float4*)&Ks[(a + 24) * ATT_STRIDE];
            float s0 = 0.f, s1 = 0.f, s2 = 0.f, s3 = 0.f;
#pragma unroll 8
            for (int i = 0; i < 64; i++) {
                const float4 qv = qp[i];
                float4 kv;
                kv = k0[i]; s0 += qv.x * kv.x + qv.y * kv.y + qv.z * kv.z + qv.w * kv.w;
                kv = k1[i]; s1 += qv.x * kv.x + qv.y * kv.y + qv.z * kv.z + qv.w * kv.w;
                kv = k2[i]; s2 += qv.x * kv.x + qv.y * kv.y + qv.z * kv.z + qv.w * kv.w;
                kv = k3[i]; s3 += qv.x * kv.x + qv.y * kv.y + qv.z * kv.z + qv.w * kv.w;
            }
            const size_t mbase = mrow + (size_t)kt * 32;
            S[q * 32 + a +  0] = s0 + mask[mbase + a +  0];
            S[q * 32 + a +  8] = s1 + mask[mbase + a +  8];
            S[q * 32 + a + 16] = s2 + mask[mbase + a + 16];
            S[q * 32 + a + 24] = s3 + mask[mbase + a + 24];
        }
        __syncthreads();

        float newm = mrun;
#pragma unroll
        for (int j = 0; j < 32; j++) newm = fmaxf(newm, S[q * 32 + j]);
        const float alpha = __expf(mrun - newm);
        lrun *= alpha;
#pragma unroll
        for (int i = 0; i < 32; i++) acc[i] *= alpha;
        float p[32];
#pragma unroll
        for (int j = 0; j < 32; j++) {
            p[j] = __expf(S[q * 32 + j] - newm);
            lrun += p[j];
        }
#pragma unroll 2
        for (int j = 0; j < 32; j++) {
            const float pj = p[j];
            const float* vrow = &Vs[j * ATT_STRIDE + a];
#pragma unroll
            for (int i = 0; i < 32; i++) acc[i] += pj * vrow[8 * i];
        }
        mrun = newm;
    }

    const float inv = 1.f / lrun;
    const size_t obase = (((size_t)b * LT + qt * 32 + q) * NH + h) * DHD;
#pragma unroll
    for (int i = 0; i < 32; i++) {
        const float val = acc[i] * inv;
        unsigned u;
        asm("cvt.rna.tf32.f32 %0, %1;" : "=r"(u) : "f"(val));  // pre-round for Wo gemm
        g_att[obase + a + 8 * i] = __uint_as_float(u);
    }
}

// ---------------- launch ----------------------------------------------------
extern "C" void kernel_launch(void* const* d_in, const int* in_sizes, int n_in,
                              void* d_out, int out_size)
{
    const float* pg   = (const float*)d_in[0];
    const float* ex   = (const float*)d_in[1];
    const float* cs   = (const float*)d_in[2];
    const float* sn   = (const float*)d_in[3];
    const float* mask = (const float*)d_in[4];
    const float* Wq0  = (const float*)d_in[5];
    const float* Wk0  = (const float*)d_in[6];
    const float* Wv0  = (const float*)d_in[7];
    const float* Wo0  = (const float*)d_in[8];
    const float* Wq1  = (const float*)d_in[9];
    const float* Wk1  = (const float*)d_in[10];
    const float* Wv1  = (const float*)d_in[11];
    const float* Wo1  = (const float*)d_in[12];
    float* out = (float*)d_out;

    float *Qd, *Kd, *Vd, *Ad;
    unsigned* Cv;
    cudaGetSymbolAddress((void**)&Qd, g_Q);
    cudaGetSymbolAddress((void**)&Kd, g_K);
    cudaGetSymbolAddress((void**)&Vd, g_V);
    cudaGetSymbolAddress((void**)&Ad, g_att);
    cudaGetSymbolAddress((void**)&Cv, g_cvt);

    cudaFuncSetAttribute(gemm_tf32, cudaFuncAttributeMaxDynamicSharedMemorySize, GSMEM_BYTES);
    cudaFuncSetAttribute(attn_kernel, cudaFuncAttributeMaxDynamicSharedMemorySize, SMEM_ATTN);

    const int MQ = NH * DHD;    // 2048
    const int MKV = NKV * DHD;  // 1024

    // --- pre-round all GEMM operands to tf32 (RNA) ---
    struct { const float* src; unsigned off; int n; } cv[10] = {
        { pg,  OFF_PG,  BB * L1C * DPG }, { ex,  OFF_EX,  BB * L2C * DEX },
        { Wq0, OFF_WQ0, MQ * DPG },       { Wk0, OFF_WK0, MKV * DPG },
        { Wv0, OFF_WV0, MKV * DPG },      { Wo0, OFF_WO0, DPG * MQ },
        { Wq1, OFF_WQ1, MQ * DEX },       { Wk1, OFF_WK1, MKV * DEX },
        { Wv1, OFF_WV1, MKV * DEX },      { Wo1, OFF_WO1, DEX * MQ },
    };
    for (int i = 0; i < 10; i++) {
        int n4 = cv[i].n / 4;
        cvt_tf32<<<(n4 + 255) / 256, 256>>>((const float4*)cv[i].src,
                                            (uint4*)(Cv + cv[i].off), n4);
    }

    // --- QKV projections, pg stream (M = 4096, K = 2304) ---
    gemm_tf32<<<dim3(MQ / 128, (BB * L1C) / 128), 256, GSMEM_BYTES>>>(
        Cv + OFF_PG, Cv + OFF_WQ0, Qd, DPG, BB * L1C, 0, 0, L1C, LT, 0, MQ);
    gemm_tf32<<<dim3(MKV / 128, (BB * L1C) / 128), 256, GSMEM_BYTES>>>(
        Cv + OFF_PG, Cv + OFF_WK0, Kd, DPG, BB * L1C, 0, 0, L1C, LT, 0, MKV);
    gemm_tf32<<<dim3(MKV / 128, (BB * L1C) / 128), 256, GSMEM_BYTES>>>(
        Cv + OFF_PG, Cv + OFF_WV0, Vd, DPG, BB * L1C, 0, 0, L1C, LT, 0, MKV);

    // --- QKV projections, ex stream (M = 2048, K = 1024) ---
    gemm_tf32<<<dim3(MQ / 128, (BB * L2C) / 128), 256, GSMEM_BYTES>>>(
        Cv + OFF_EX, Cv + OFF_WQ1, Qd, DEX, BB * L2C, 0, 0, L2C, LT, L1C, MQ);
    gemm_tf32<<<dim3(MKV / 128, (BB * L2C) / 128), 256, GSMEM_BYTES>>>(
        Cv + OFF_EX, Cv + OFF_WK1, Kd, DEX, BB * L2C, 0, 0, L2C, LT, L1C, MKV);
    gemm_tf32<<<dim3(MKV / 128, (BB * L2C) / 128), 256, GSMEM_BYTES>>>(
        Cv + OFF_EX, Cv + OFF_WV1, Vd, DEX, BB * L2C, 0, 0, L2C, LT, L1C, MKV);

    // --- RoPE (fold softmax scale into Q) ---
    rope_kernel<<<dim3(NH, LT, BB), DHD / 2>>>(Qd, cs, sn, NH, QK_SCALE);
    rope_kernel<<<dim3(NKV, LT, BB), DHD / 2>>>(Kd, cs, sn, NKV, 1.0f);

    // --- attention ---
    attn_kernel<<<dim3(LT / 32, NH, BB), 256, SMEM_ATTN>>>(mask);

    // --- output projections ---
    gemm_tf32<<<dim3(DPG / 128, (BB * L1C) / 128), 256, GSMEM_BYTES>>>(
        (const unsigned*)Ad, Cv + OFF_WO0, out, MQ, L1C, LT, 0, BB * L1C, 0, 0, DPG);
    gemm_tf32<<<dim3(DEX / 128, (BB * L2C) / 128), 256, GSMEM_BYTES>>>(
        (const unsigned*)Ad, Cv + OFF_WO1, out + (size_t)BB * L1C * DPG, MQ,
        L2C, LT, L1C, BB * L2C, 0, 0, DEX);
}